// round 9
// baseline (speedup 1.0000x reference)
#include <cuda_runtime.h>
#include <math.h>
#include <stdint.h>

#define BATCH  256
#define D      512
#define S      196
#define NKQ    16           // gemm k-slices (32 e each)
#define NOCT   8            // octs per batch in fused kernel (64 d-rows each)
#define OROWS  64           // rows per oct

// device scratch (no allocs allowed)
__device__ float g_vp[NKQ][BATCH][D];        // k-slice partials of v = u @ W (8 MB)
__device__ float g_rai[BATCH][NOCT][256];    // per-oct partial logits (2 MB)
__device__ unsigned int g_cnt[BATCH];        // per-batch completion counters

__device__ __forceinline__ void cp_async16(uint32_t saddr, const void* gaddr) {
    asm volatile("cp.async.cg.shared.global [%0], [%1], 16;"
                 :: "r"(saddr), "l"(gaddr) : "memory");
}
__device__ __forceinline__ uint32_t smem_u32(const void* p) {
    return (uint32_t)__cvta_generic_to_shared(p);
}

// ---------------------------------------------------------------------------
// GEMM partials: g_vp[kq][b][d] = sum_{e in 32-slice} (ctrl[b,e]*w_attn[e])*W[e,d].
// Grid (32 b-tiles, 16 k-slices), 256 threads; 8b x 4d register tile/thread.
// Also zeroes g_cnt for the fused kernel (stream-ordered).
// ---------------------------------------------------------------------------
__global__ __launch_bounds__(256) void gemm_kernel(
    const float* __restrict__ ctrl,
    const float* __restrict__ W,
    const float* __restrict__ w_attn)
{
    __shared__ __align__(16) float u_s[32 * 8];
    __shared__ __align__(16) float part[8 * 512];

    const int tid = threadIdx.x;
    const int dl  = tid & 127;
    const int eh  = tid >> 7;
    const int b0  = blockIdx.x * 8;
    const int kq  = blockIdx.y;
    const int e0  = kq * 32;
    const int d0  = dl * 4;

    if (blockIdx.x == 0 && blockIdx.y == 0 && tid < BATCH)
        g_cnt[tid] = 0;

    {
        int el = tid & 31, j = tid >> 5;
        u_s[el * 8 + j] = ctrl[(b0 + j) * D + e0 + el] * w_attn[e0 + el];
    }
    __syncthreads();

    float acc[8][4];
#pragma unroll
    for (int j = 0; j < 8; j++)
#pragma unroll
        for (int i = 0; i < 4; i++) acc[j][i] = 0.f;

#pragma unroll 4
    for (int i = 0; i < 16; i++) {
        const int el = eh * 16 + i;
        const float4 w4 = *reinterpret_cast<const float4*>(W + (size_t)(e0 + el) * D + d0);
        const float4 ua = *reinterpret_cast<const float4*>(&u_s[el * 8]);
        const float4 ub = *reinterpret_cast<const float4*>(&u_s[el * 8 + 4]);
        acc[0][0] += ua.x * w4.x; acc[0][1] += ua.x * w4.y; acc[0][2] += ua.x * w4.z; acc[0][3] += ua.x * w4.w;
        acc[1][0] += ua.y * w4.x; acc[1][1] += ua.y * w4.y; acc[1][2] += ua.y * w4.z; acc[1][3] += ua.y * w4.w;
        acc[2][0] += ua.z * w4.x; acc[2][1] += ua.z * w4.y; acc[2][2] += ua.z * w4.z; acc[2][3] += ua.z * w4.w;
        acc[3][0] += ua.w * w4.x; acc[3][1] += ua.w * w4.y; acc[3][2] += ua.w * w4.z; acc[3][3] += ua.w * w4.w;
        acc[4][0] += ub.x * w4.x; acc[4][1] += ub.x * w4.y; acc[4][2] += ub.x * w4.z; acc[4][3] += ub.x * w4.w;
        acc[5][0] += ub.y * w4.x; acc[5][1] += ub.y * w4.y; acc[5][2] += ub.y * w4.z; acc[5][3] += ub.y * w4.w;
        acc[6][0] += ub.z * w4.x; acc[6][1] += ub.z * w4.y; acc[6][2] += ub.z * w4.z; acc[6][3] += ub.z * w4.w;
        acc[7][0] += ub.w * w4.x; acc[7][1] += ub.w * w4.y; acc[7][2] += ub.w * w4.z; acc[7][3] += ub.w * w4.w;
    }

    if (eh == 1) {
#pragma unroll
        for (int j = 0; j < 8; j++)
            *reinterpret_cast<float4*>(&part[j * 512 + d0]) =
                make_float4(acc[j][0], acc[j][1], acc[j][2], acc[j][3]);
    }
    __syncthreads();
    if (eh == 0) {
#pragma unroll
        for (int j = 0; j < 8; j++) {
            float4 p = *reinterpret_cast<const float4*>(&part[j * 512 + d0]);
            *reinterpret_cast<float4*>(&g_vp[kq][b0 + j][d0]) =
                make_float4(acc[j][0] + p.x, acc[j][1] + p.y,
                            acc[j][2] + p.z, acc[j][3] + p.w);
        }
    }
}

// ---------------------------------------------------------------------------
// Fused kernel, smem-staged. Grid 2048 = (b, oct): CTA stages its 64-row
// (50 KB, contiguous) kb tile via cp.async, computes partial logits from
// smem, signals, one thread spins for the other 7 octs, softmaxes, and does
// the weighted sum from smem. kb read from DRAM exactly once.
// ---------------------------------------------------------------------------
__global__ __launch_bounds__(256) void fused_kernel(
    const float* __restrict__ kb,      // [B, D, S]
    const float* __restrict__ memory,
    const float* __restrict__ ctrl,
    const float* __restrict__ w_attn,
    float* __restrict__ out)           // [B, D]
{
    extern __shared__ __align__(16) float kb_s[];   // OROWS * S floats = 50176 B

    const int oct  = blockIdx.x & 7;
    const int b    = blockIdx.x >> 3;
    const int tid  = threadIdx.x;
    const int wid  = tid >> 5;
    const int lane = tid & 31;
    const int l2   = lane < 17 ? lane : 16;     // clamped second segment
    const float mB = lane < 17 ? 1.f : 0.f;

    __shared__ float w_s[OROWS];
    __shared__ __align__(16) float part[4][200];
    __shared__ __align__(16) float rvi_s[208];
    __shared__ float red[8];

    const float* __restrict__ gsrc = kb + (size_t)b * (D * S) + (size_t)oct * (OROWS * S);

    // ---- stage tile: 3136 x 16B contiguous cp.async ----
    {
        const uint32_t sbase = smem_u32(kb_s);
#pragma unroll 13
        for (int idx = tid; idx < (OROWS * S) / 4; idx += 256)
            cp_async16(sbase + idx * 16, gsrc + idx * 4);
        asm volatile("cp.async.commit_group;" ::: "memory");
    }

    // ---- finalize w for my 64 rows while the copy flies ----
    if (tid < OROWS) {
        const int dg = oct * OROWS + tid;
        float v = 0.f;
#pragma unroll
        for (int k = 0; k < NKQ; k++) v += g_vp[k][b][dg];
        w_s[tid] = memory[b * D + dg] * v + ctrl[b * D + dg] * w_attn[dg];
    }

    asm volatile("cp.async.wait_group 0;" ::: "memory");
    __syncthreads();

    // ---- Pass 1: partial logits from smem (8 rows per warp) ----
    float4 accA = make_float4(0.f, 0.f, 0.f, 0.f);
    float4 accB = make_float4(0.f, 0.f, 0.f, 0.f);

#pragma unroll
    for (int r = wid; r < OROWS; r += 8) {
        const float wv = w_s[r];
        const float4* __restrict__ row = reinterpret_cast<const float4*>(&kb_s[r * S]);
        float4 va = row[lane];          // s = 4*lane..+3
        float4 vb = row[32 + l2];       // s = 128+4*l2..+3
        accA.x += wv * va.x;  accA.y += wv * va.y;
        accA.z += wv * va.z;  accA.w += wv * va.w;
        float wb = wv * mB;
        accB.x += wb * vb.x;  accB.y += wb * vb.y;
        accB.z += wb * vb.z;  accB.w += wb * vb.w;
    }

    // two-round cross-warp reduction (deterministic): 4..7 store, 0..3 add
    if (wid >= 4) {
        *reinterpret_cast<float4*>(&part[wid - 4][4 * lane]) = accA;
        if (lane < 17)
            *reinterpret_cast<float4*>(&part[wid - 4][128 + 4 * lane]) = accB;
    }
    __syncthreads();
    if (wid < 4) {
        float4 pA = *reinterpret_cast<const float4*>(&part[wid][4 * lane]);
        accA.x += pA.x; accA.y += pA.y; accA.z += pA.z; accA.w += pA.w;
        *reinterpret_cast<float4*>(&part[wid][4 * lane]) = accA;
        if (lane < 17) {
            float4 pB = *reinterpret_cast<const float4*>(&part[wid][128 + 4 * lane]);
            accB.x += pB.x; accB.y += pB.y; accB.z += pB.z; accB.w += pB.w;
            *reinterpret_cast<float4*>(&part[wid][128 + 4 * lane]) = accB;
        }
    }
    __syncthreads();

    if (tid < S)
        g_rai[b][oct][tid] = part[0][tid] + part[1][tid] + part[2][tid] + part[3][tid];
    __syncthreads();

    // ---- signal + single-thread spin: all 8 octs of batch b done? ----
    if (tid == 0) {
        __threadfence();                               // release g_rai
        atomicAdd(&g_cnt[b], 1u);
        unsigned v;
        do {
            asm volatile("ld.acquire.gpu.global.u32 %0, [%1];"
                         : "=r"(v) : "l"(&g_cnt[b]) : "memory");
            if (v < (unsigned)NOCT) __nanosleep(128);
        } while (v < (unsigned)NOCT);
    }
    __syncthreads();   // chains tid0's acquire to the whole block

    // full rai = fixed-order sum of 8 oct-partials (deterministic)
    float rai = -INFINITY;
    if (tid < S) {
        float sum = 0.f;
#pragma unroll
        for (int k = 0; k < NOCT; k++) sum += g_rai[b][k][tid];
        rai = sum;
    }

    // ---- softmax over s ----
    float m = rai;
#pragma unroll
    for (int off = 16; off > 0; off >>= 1)
        m = fmaxf(m, __shfl_xor_sync(0xffffffff, m, off));
    if (lane == 0) red[wid] = m;
    __syncthreads();
    if (wid == 0) {
        float v = (lane < 8) ? red[lane] : -INFINITY;
#pragma unroll
        for (int off = 4; off > 0; off >>= 1)
            v = fmaxf(v, __shfl_xor_sync(0xffffffff, v, off));
        if (lane == 0) red[0] = v;
    }
    __syncthreads();
    const float gmax = red[0];
    __syncthreads();

    float p = (tid < S) ? expf(rai - gmax) : 0.f;
    float sacc = p;
#pragma unroll
    for (int off = 16; off > 0; off >>= 1)
        sacc += __shfl_xor_sync(0xffffffff, sacc, off);
    if (lane == 0) red[wid] = sacc;
    __syncthreads();
    if (wid == 0) {
        float v = (lane < 8) ? red[lane] : 0.f;
#pragma unroll
        for (int off = 4; off > 0; off >>= 1)
            v += __shfl_xor_sync(0xffffffff, v, off);
        if (lane == 0) red[0] = v;
    }
    __syncthreads();
    const float inv_sum = 1.f / red[0];
    if (tid < S) rvi_s[tid] = p * inv_sum;
    if (tid >= S && tid < 208) rvi_s[tid] = 0.f;
    __syncthreads();

    const float4 rA = *reinterpret_cast<const float4*>(&rvi_s[4 * lane]);
    const float4 rB = *reinterpret_cast<const float4*>(&rvi_s[128 + 4 * l2]);

    // ---- Pass 2: weighted sum from smem (8 rows per warp) ----
#pragma unroll
    for (int r = wid; r < OROWS; r += 8) {
        const float4* __restrict__ row = reinterpret_cast<const float4*>(&kb_s[r * S]);
        float4 va = row[lane];
        float4 vb = row[32 + l2];
        float sum = va.x * rA.x + va.y * rA.y + va.z * rA.z + va.w * rA.w
                  + mB * (vb.x * rB.x + vb.y * rB.y + vb.z * rB.z + vb.w * rB.w);
#pragma unroll
        for (int off = 16; off > 0; off >>= 1)
            sum += __shfl_xor_sync(0xffffffff, sum, off);
        if (lane == 0) out[b * D + oct * OROWS + r] = sum;
    }
}

extern "C" void kernel_launch(void* const* d_in, const int* in_sizes, int n_in,
                              void* d_out, int out_size)
{
    const float* memory = (const float*)d_in[0];  // [B, D]
    const float* ctrl   = (const float*)d_in[1];  // [B, D]
    const float* kb     = (const float*)d_in[2];  // [B, D, S]
    const float* W      = (const float*)d_in[3];  // [D, D]
    // d_in[4] = b_concat: s-independent shift inside softmax -> drops out
    const float* w_attn = (const float*)d_in[5];  // [D]
    float* out = (float*)d_out;                   // [B, D]

    const int tile_smem = OROWS * S * sizeof(float);  // 50176 B
    cudaFuncSetAttribute(fused_kernel,
                         cudaFuncAttributeMaxDynamicSharedMemorySize, tile_smem);

    gemm_kernel<<<dim3(32, NKQ), 256>>>(ctrl, W, w_attn);
    fused_kernel<<<NOCT * BATCH, 256, tile_smem>>>(kb, memory, ctrl, w_attn, out);
}